// round 9
// baseline (speedup 1.0000x reference)
#include <cuda_runtime.h>

// GlobalFilter: y = irfft2(rfft2(x, ortho) * W, ortho)
// x: [128,14,14,768] f32, W: [14,8,768,2] f32.
// R9 = R8 + ILP-first config: 3 CTAs/SM (~84 regs) + batched weight
//      prefetch in pass B. Structure/work identical to R8.

#define CC  768
#define CB  32
#define NTH 256

typedef unsigned long long ull;

__device__ __forceinline__ ull pk(float lo, float hi) {
    ull r; asm("mov.b64 %0, {%1,%2};" : "=l"(r) : "f"(lo), "f"(hi)); return r;
}
__device__ __forceinline__ void upk(ull v, float& lo, float& hi) {
    asm("mov.b64 {%0,%1}, %2;" : "=f"(lo), "=f"(hi) : "l"(v));
}
__device__ __forceinline__ ull f2fma(ull a, ull b, ull c) {
    ull d; asm("fma.rn.f32x2 %0, %1, %2, %3;" : "=l"(d) : "l"(a), "l"(b), "l"(c)); return d;
}
__device__ __forceinline__ ull f2add(ull a, ull b) {
    ull d; asm("add.rn.f32x2 %0, %1, %2;" : "=l"(d) : "l"(a), "l"(b)); return d;
}
__device__ __forceinline__ ull f2sub(ull a, ull b) {
    ull d; asm("sub.rn.f32x2 %0, %1, %2;" : "=l"(d) : "l"(a), "l"(b)); return d;
}
__host__ __device__ constexpr ull pkc(float lo, float hi) {
    return (ull)__builtin_bit_cast(unsigned int, lo)
         | ((ull)__builtin_bit_cast(unsigned int, hi) << 32);
}
// complex multiply (packed X) by packed weight (wr, wi)
__device__ __forceinline__ ull cmulw(ull X, ull w) {
    float xr, xi, wr, wi;
    upk(X, xr, xi); upk(w, wr, wi);
    return pk(fmaf(-xi, wi, xr * wr), fmaf(xi, wr, xr * wi));
}
__device__ __forceinline__ void stcs(float* p, float v) {
    asm volatile("st.global.cs.f32 [%0], %1;" :: "l"(p), "f"(v) : "memory");
}

#define DEF_TWIDDLES \
    constexpr float COS14[14] = { \
         1.0f,                 0.9009688679024191f,  0.6234898018587336f, \
         0.22252093395631445f,-0.22252093395631445f,-0.6234898018587336f, \
        -0.9009688679024191f, -1.0f,                -0.9009688679024191f, \
        -0.6234898018587336f, -0.22252093395631445f, 0.22252093395631445f, \
         0.6234898018587336f,  0.9009688679024191f }; \
    constexpr float SIN14[14] = { \
         0.0f,                 0.43388373911755823f, 0.7818314824680298f, \
         0.9749279121818236f,  0.9749279121818236f,  0.7818314824680298f, \
         0.43388373911755823f, 0.0f,                -0.43388373911755823f, \
        -0.7818314824680298f, -0.9749279121818236f, -0.9749279121818236f, \
        -0.7818314824680298f, -0.43388373911755823f }

__global__ __launch_bounds__(NTH, 3)
void gfilter_kernel(const float* __restrict__ x,
                    const float* __restrict__ wt,
                    float* __restrict__ y)
{
    DEF_TWIDDLES;
    constexpr float INV98  = 1.0f / 98.0f;
    constexpr float INV196 = 1.0f / 196.0f;
    extern __shared__ ull sbuf[];   // 112 slots x 32 channels, 8B each

    const int tid  = threadIdx.x;
    const int cl   = tid & 31;
    const int role = tid >> 5;      // 0..7, one warp per role
    const int b    = blockIdx.y;
    const int c    = blockIdx.x * CB + cl;

    ull* bufc = sbuf + cl;          // index: slot*32; slot = h*8 + kw
    const int base = (b * 196) * CC + c;
    const float* xb = x + base;

    // ---- Pass A: rfft over W on rows read straight from global -------------
    #pragma unroll
    for (int i = 0; i < 2; ++i) {
        const int h = role + 8 * i;
        if (i == 0 || role < 6) {
            float xv[14];
            #pragma unroll
            for (int w = 0; w < 14; ++w)
                xv[w] = __ldg(&xb[(h * 14 + w) * CC]);
            ull eo[7];
            #pragma unroll
            for (int j = 1; j <= 6; ++j)
                eo[j] = pk(xv[j] + xv[14 - j], xv[j] - xv[14 - j]);
            const float be = xv[0] + xv[7], bo = xv[0] - xv[7];
            #pragma unroll
            for (int kw = 0; kw < 8; ++kw) {
                ull acc = pk((kw & 1) ? bo : be, 0.f);   // (re, im)
                #pragma unroll
                for (int j = 1; j <= 6; ++j) {
                    const int m = (kw * j) % 14;
                    acc = f2fma(eo[j], pkc(COS14[m], -SIN14[m]), acc);
                }
                bufc[(h * 8 + kw) * 32] = acc;
            }
        }
    }
    __syncthreads();

    // ---- Pass B: fwd H-DFT + weight + inv H-DFT, one kw column per warp ----
    {
        const int kw = role;
        const float2* wt2c = reinterpret_cast<const float2*>(wt) + c;

        // Batched prefetch: all 14 weights for this column (independent LDGs)
        ull W[14];
        #pragma unroll
        for (int r = 0; r < 14; ++r) {
            const float2 wv = __ldg(&wt2c[(r * 8 + kw) * CC]);
            W[r] = pk(wv.x, wv.y);
        }
        // Batched F loads
        ull F[14];
        #pragma unroll
        for (int h = 0; h < 14; ++h)
            F[h] = bufc[(h * 8 + kw) * 32];
        // forward folds over h
        ull E[7], O[7];
        #pragma unroll
        for (int j = 1; j <= 6; ++j) {
            E[j] = f2add(F[j], F[14 - j]);
            O[j] = f2sub(F[j], F[14 - j]);
        }
        const ull fbp = f2add(F[0], F[7]);
        const ull fbm = f2sub(F[0], F[7]);

        // forward per kh-pair, weight-multiply, fold for inverse on the fly
        ull X0, X7, EZ[7], OZ[7];
        #pragma unroll
        for (int kh = 0; kh < 8; ++kh) {
            ull Cacc = (kh & 1) ? fbm : fbp;  // (Cr, Ci)
            ull Sacc = 0ull;                  // (Sr, Si)
            #pragma unroll
            for (int j = 1; j <= 6; ++j) {
                const int m = (kh * j) % 14;
                Cacc = f2fma(E[j], pkc(COS14[m], COS14[m]), Cacc);
                if ((m % 7) != 0)
                    Sacc = f2fma(O[j], pkc(SIN14[m], SIN14[m]), Sacc);
            }
            float sr, si; upk(Sacc, sr, si);
            // X[kh] = C - iS ; X[14-kh] = C + iS
            ull Xa = f2add(Cacc, pk(si, -sr));
            Xa = cmulw(Xa, W[kh]);
            if (kh == 0)      X0 = Xa;
            else if (kh == 7) X7 = Xa;
            else {
                ull Xb = f2add(Cacc, pk(-si, sr));
                Xb = cmulw(Xb, W[14 - kh]);
                EZ[kh] = f2add(Xa, Xb);
                OZ[kh] = f2sub(Xa, Xb);
            }
        }
        // inverse H-DFT (e^{+i}), h paired with 14-h; write back to same column
        const ull ibp = f2add(X0, X7);
        const ull ibm = f2sub(X0, X7);
        #pragma unroll
        for (int h = 0; h < 8; ++h) {
            ull Cacc = (h & 1) ? ibm : ibp;
            ull Sacc = 0ull;
            #pragma unroll
            for (int j = 1; j <= 6; ++j) {
                const int m = (j * h) % 14;
                Cacc = f2fma(EZ[j], pkc(COS14[m], COS14[m]), Cacc);
                if ((m % 7) != 0)
                    Sacc = f2fma(OZ[j], pkc(SIN14[m], SIN14[m]), Sacc);
            }
            float sr, si; upk(Sacc, sr, si);
            bufc[(h * 8 + kw) * 32] = f2add(Cacc, pk(-si, sr));
            if (h >= 1 && h <= 6)
                bufc[((14 - h) * 8 + kw) * 32] = f2add(Cacc, pk(si, -sr));
        }
    }
    __syncthreads();

    // ---- Pass C: c2r over W (w-paired), scale folded into constants --------
    float* yb = y + base;
    #pragma unroll
    for (int i = 0; i < 2; ++i) {
        const int h = role + 8 * i;
        if (i == 0 || role < 6) {
            ull yv[8];
            #pragma unroll
            for (int kw = 0; kw < 8; ++kw)
                yv[kw] = bufc[(h * 8 + kw) * 32];
            float yr0, yi0, yr7, yi7;
            upk(yv[0], yr0, yi0); upk(yv[7], yr7, yi7);
            const float b0 = yr0 * INV196, b7 = yr7 * INV196;
            const float bse_e = b0 + b7, bse_o = b0 - b7;
            #pragma unroll
            for (int w = 0; w < 8; ++w) {
                // acc = (C, S) with pre-scaled twiddles; seeded with base in C
                ull acc = pk((w & 1) ? bse_o : bse_e, 0.f);
                #pragma unroll
                for (int kw = 1; kw <= 6; ++kw) {
                    const int m = (kw * w) % 14;
                    acc = f2fma(yv[kw], pkc(COS14[m] * INV98, SIN14[m] * INV98), acc);
                }
                float Cv, Sv; upk(acc, Cv, Sv);
                stcs(&yb[(h * 14 + w) * CC], Cv - Sv);
                if (w >= 1 && w <= 6)
                    stcs(&yb[(h * 14 + 14 - w) * CC], Cv + Sv);
            }
        }
    }
}

extern "C" void kernel_launch(void* const* d_in, const int* in_sizes, int n_in,
                              void* d_out, int out_size)
{
    (void)in_sizes; (void)n_in; (void)out_size;
    const float* x  = (const float*)d_in[0];
    const float* wt = (const float*)d_in[1];
    float* y        = (float*)d_out;

    const int smem_bytes = 112 * CB * (int)sizeof(ull); // 28672
    dim3 grid(CC / CB, 128); // (24, 128)
    gfilter_kernel<<<grid, NTH, smem_bytes>>>(x, wt, y);
}

// round 10
// speedup vs baseline: 1.0556x; 1.0556x over previous
#include <cuda_runtime.h>

// GlobalFilter: y = irfft2(rfft2(x, ortho) * W, ortho)
// x: [128,14,14,768] f32, W: [14,8,768,2] f32.
// R10 = R8 (best) + swapped-sine accumulation in pass B: the S-sum is
//       accumulated directly as T=(Si,-Sr) via pre-swapped odd folds, so
//       X = C -/+ iS becomes f2add/f2sub(C,T) -- no per-iteration
//       upk/neg/pk register shuffling. Structure/work otherwise identical.

#define CC  768
#define CB  32
#define NTH 256

typedef unsigned long long ull;

__device__ __forceinline__ ull pk(float lo, float hi) {
    ull r; asm("mov.b64 %0, {%1,%2};" : "=l"(r) : "f"(lo), "f"(hi)); return r;
}
__device__ __forceinline__ void upk(ull v, float& lo, float& hi) {
    asm("mov.b64 {%0,%1}, %2;" : "=f"(lo), "=f"(hi) : "l"(v));
}
__device__ __forceinline__ ull swp(ull v) {      // (lo,hi) -> (hi,lo)
    float lo, hi; upk(v, lo, hi); return pk(hi, lo);
}
__device__ __forceinline__ ull f2fma(ull a, ull b, ull c) {
    ull d; asm("fma.rn.f32x2 %0, %1, %2, %3;" : "=l"(d) : "l"(a), "l"(b), "l"(c)); return d;
}
__device__ __forceinline__ ull f2add(ull a, ull b) {
    ull d; asm("add.rn.f32x2 %0, %1, %2;" : "=l"(d) : "l"(a), "l"(b)); return d;
}
__device__ __forceinline__ ull f2sub(ull a, ull b) {
    ull d; asm("sub.rn.f32x2 %0, %1, %2;" : "=l"(d) : "l"(a), "l"(b)); return d;
}
__host__ __device__ constexpr ull pkc(float lo, float hi) {
    return (ull)__builtin_bit_cast(unsigned int, lo)
         | ((ull)__builtin_bit_cast(unsigned int, hi) << 32);
}
// complex multiply (packed X) by packed weight (wr, wi)
__device__ __forceinline__ ull cmulw(ull X, ull w) {
    float xr, xi, wr, wi;
    upk(X, xr, xi); upk(w, wr, wi);
    return pk(fmaf(-xi, wi, xr * wr), fmaf(xi, wr, xr * wi));
}
__device__ __forceinline__ void stcs(float* p, float v) {
    asm volatile("st.global.cs.f32 [%0], %1;" :: "l"(p), "f"(v) : "memory");
}

#define DEF_TWIDDLES \
    constexpr float COS14[14] = { \
         1.0f,                 0.9009688679024191f,  0.6234898018587336f, \
         0.22252093395631445f,-0.22252093395631445f,-0.6234898018587336f, \
        -0.9009688679024191f, -1.0f,                -0.9009688679024191f, \
        -0.6234898018587336f, -0.22252093395631445f, 0.22252093395631445f, \
         0.6234898018587336f,  0.9009688679024191f }; \
    constexpr float SIN14[14] = { \
         0.0f,                 0.43388373911755823f, 0.7818314824680298f, \
         0.9749279121818236f,  0.9749279121818236f,  0.7818314824680298f, \
         0.43388373911755823f, 0.0f,                -0.43388373911755823f, \
        -0.7818314824680298f, -0.9749279121818236f, -0.9749279121818236f, \
        -0.7818314824680298f, -0.43388373911755823f }

__global__ __launch_bounds__(NTH, 4)
void gfilter_kernel(const float* __restrict__ x,
                    const float* __restrict__ wt,
                    float* __restrict__ y)
{
    DEF_TWIDDLES;
    constexpr float INV98  = 1.0f / 98.0f;
    constexpr float INV196 = 1.0f / 196.0f;
    extern __shared__ ull sbuf[];   // 112 slots x 32 channels, 8B each

    const int tid  = threadIdx.x;
    const int cl   = tid & 31;
    const int role = tid >> 5;      // 0..7, one warp per role
    const int b    = blockIdx.y;
    const int c    = blockIdx.x * CB + cl;

    ull* bufc = sbuf + cl;          // index: slot*32; slot = h*8 + kw
    const int base = (b * 196) * CC + c;
    const float* xb = x + base;

    // ---- Pass A: rfft over W on rows read straight from global -------------
    #pragma unroll
    for (int i = 0; i < 2; ++i) {
        const int h = role + 8 * i;
        if (i == 0 || role < 6) {
            float xv[14];
            #pragma unroll
            for (int w = 0; w < 14; ++w)
                xv[w] = __ldg(&xb[(h * 14 + w) * CC]);
            ull eo[7];
            #pragma unroll
            for (int j = 1; j <= 6; ++j)
                eo[j] = pk(xv[j] + xv[14 - j], xv[j] - xv[14 - j]);
            const float be = xv[0] + xv[7], bo = xv[0] - xv[7];
            #pragma unroll
            for (int kw = 0; kw < 8; ++kw) {
                ull acc = pk((kw & 1) ? bo : be, 0.f);   // (re, im)
                #pragma unroll
                for (int j = 1; j <= 6; ++j) {
                    const int m = (kw * j) % 14;
                    acc = f2fma(eo[j], pkc(COS14[m], -SIN14[m]), acc);
                }
                bufc[(h * 8 + kw) * 32] = acc;
            }
        }
    }
    __syncthreads();

    // ---- Pass B: fwd H-DFT + weight + inv H-DFT, one kw column per warp ----
    {
        const int kw = role;
        ull F[14];
        #pragma unroll
        for (int h = 0; h < 14; ++h)
            F[h] = bufc[(h * 8 + kw) * 32];

        // forward folds over h; odd fold pre-swapped: OS[j] = (oi, or)
        ull E[7], OS[7];
        #pragma unroll
        for (int j = 1; j <= 6; ++j) {
            E[j]  = f2add(F[j], F[14 - j]);
            OS[j] = swp(f2sub(F[j], F[14 - j]));
        }
        const ull fbp = f2add(F[0], F[7]);
        const ull fbm = f2sub(F[0], F[7]);

        const float2* wt2c = reinterpret_cast<const float2*>(wt) + c;

        // forward per kh-pair, weight-multiply, fold for inverse on the fly
        // T = sum OS[j]*(s,-s) = (Si, -Sr); X[kh] = C+T, X[14-kh] = C-T
        ull X0, X7, EZ[7], OZS[7];
        #pragma unroll
        for (int kh = 0; kh < 8; ++kh) {
            ull Cacc = (kh & 1) ? fbm : fbp;  // (Cr, Ci)
            ull Tacc = 0ull;                  // (Si, -Sr)
            #pragma unroll
            for (int j = 1; j <= 6; ++j) {
                const int m = (kh * j) % 14;
                Cacc = f2fma(E[j], pkc(COS14[m], COS14[m]), Cacc);
                if ((m % 7) != 0)
                    Tacc = f2fma(OS[j], pkc(SIN14[m], -SIN14[m]), Tacc);
            }
            ull Xa = cmulw(f2add(Cacc, Tacc),
                           pk(wt2c[(kh * 8 + kw) * CC].x,
                              wt2c[(kh * 8 + kw) * CC].y));
            if (kh == 0)      X0 = Xa;
            else if (kh == 7) X7 = Xa;
            else {
                ull Xb = cmulw(f2sub(Cacc, Tacc),
                               pk(wt2c[((14 - kh) * 8 + kw) * CC].x,
                                  wt2c[((14 - kh) * 8 + kw) * CC].y));
                EZ[kh]  = f2add(Xa, Xb);
                OZS[kh] = swp(f2sub(Xa, Xb));   // (ozi, ozr)
            }
        }
        // inverse H-DFT: T' = sum OZS*(s,-s) = (Si', -Sr')
        // Y_h = C - T', Y_{14-h} = C + T'
        const ull ibp = f2add(X0, X7);
        const ull ibm = f2sub(X0, X7);
        #pragma unroll
        for (int h = 0; h < 8; ++h) {
            ull Cacc = (h & 1) ? ibm : ibp;
            ull Tacc = 0ull;
            #pragma unroll
            for (int j = 1; j <= 6; ++j) {
                const int m = (j * h) % 14;
                Cacc = f2fma(EZ[j], pkc(COS14[m], COS14[m]), Cacc);
                if ((m % 7) != 0)
                    Tacc = f2fma(OZS[j], pkc(SIN14[m], -SIN14[m]), Tacc);
            }
            bufc[(h * 8 + kw) * 32] = f2sub(Cacc, Tacc);
            if (h >= 1 && h <= 6)
                bufc[((14 - h) * 8 + kw) * 32] = f2add(Cacc, Tacc);
        }
    }
    __syncthreads();

    // ---- Pass C: c2r over W (w-paired), scale folded into constants --------
    float* yb = y + base;
    #pragma unroll
    for (int i = 0; i < 2; ++i) {
        const int h = role + 8 * i;
        if (i == 0 || role < 6) {
            ull yv[8];
            #pragma unroll
            for (int kw = 0; kw < 8; ++kw)
                yv[kw] = bufc[(h * 8 + kw) * 32];
            float yr0, yi0, yr7, yi7;
            upk(yv[0], yr0, yi0); upk(yv[7], yr7, yi7);
            const float b0 = yr0 * INV196, b7 = yr7 * INV196;
            const float bse_e = b0 + b7, bse_o = b0 - b7;
            #pragma unroll
            for (int w = 0; w < 8; ++w) {
                // acc = (C, S) with pre-scaled twiddles; seeded with base in C
                ull acc = pk((w & 1) ? bse_o : bse_e, 0.f);
                #pragma unroll
                for (int kw = 1; kw <= 6; ++kw) {
                    const int m = (kw * w) % 14;
                    acc = f2fma(yv[kw], pkc(COS14[m] * INV98, SIN14[m] * INV98), acc);
                }
                float Cv, Sv; upk(acc, Cv, Sv);
                stcs(&yb[(h * 14 + w) * CC], Cv - Sv);
                if (w >= 1 && w <= 6)
                    stcs(&yb[(h * 14 + 14 - w) * CC], Cv + Sv);
            }
        }
    }
}

extern "C" void kernel_launch(void* const* d_in, const int* in_sizes, int n_in,
                              void* d_out, int out_size)
{
    (void)in_sizes; (void)n_in; (void)out_size;
    const float* x  = (const float*)d_in[0];
    const float* wt = (const float*)d_in[1];
    float* y        = (float*)d_out;

    const int smem_bytes = 112 * CB * (int)sizeof(ull); // 28672
    dim3 grid(CC / CB, 128); // (24, 128)
    gfilter_kernel<<<grid, NTH, smem_bytes>>>(x, wt, y);
}

// round 11
// speedup vs baseline: 1.1167x; 1.0579x over previous
#include <cuda_runtime.h>

// GlobalFilter: y = irfft2(rfft2(x, ortho) * W, ortho)
// x: [128,14,14,768] f32, W: [14,8,768,2] f32.
// R11 = R10 + second trig fold: cos(k(7-j)) = (-1)^k cos(kj),
//       sin(k(7-j)) = -(-1)^k sin(kj)  =>  all 6-term DFT sums become
//       3-term sums over parity folds (~25% fewer FMA-pipe ops).
//       Structure, smem layout, occupancy identical to R8/R10.

#define CC  768
#define CB  32
#define NTH 256

typedef unsigned long long ull;

__device__ __forceinline__ ull pk(float lo, float hi) {
    ull r; asm("mov.b64 %0, {%1,%2};" : "=l"(r) : "f"(lo), "f"(hi)); return r;
}
__device__ __forceinline__ void upk(ull v, float& lo, float& hi) {
    asm("mov.b64 {%0,%1}, %2;" : "=f"(lo), "=f"(hi) : "l"(v));
}
__device__ __forceinline__ ull swp(ull v) {      // (lo,hi) -> (hi,lo)
    float lo, hi; upk(v, lo, hi); return pk(hi, lo);
}
__device__ __forceinline__ ull f2fma(ull a, ull b, ull c) {
    ull d; asm("fma.rn.f32x2 %0, %1, %2, %3;" : "=l"(d) : "l"(a), "l"(b), "l"(c)); return d;
}
__device__ __forceinline__ ull f2add(ull a, ull b) {
    ull d; asm("add.rn.f32x2 %0, %1, %2;" : "=l"(d) : "l"(a), "l"(b)); return d;
}
__device__ __forceinline__ ull f2sub(ull a, ull b) {
    ull d; asm("sub.rn.f32x2 %0, %1, %2;" : "=l"(d) : "l"(a), "l"(b)); return d;
}
__host__ __device__ constexpr ull pkc(float lo, float hi) {
    return (ull)__builtin_bit_cast(unsigned int, lo)
         | ((ull)__builtin_bit_cast(unsigned int, hi) << 32);
}
#define CP(v) pkc(v, v)
// complex multiply (packed X) by packed weight (wr, wi)
__device__ __forceinline__ ull cmulw(ull X, ull w) {
    float xr, xi, wr, wi;
    upk(X, xr, xi); upk(w, wr, wi);
    return pk(fmaf(-xi, wi, xr * wr), fmaf(xi, wr, xr * wi));
}
__device__ __forceinline__ void stcs(float* p, float v) {
    asm volatile("st.global.cs.f32 [%0], %1;" :: "l"(p), "f"(v) : "memory");
}

#define DEF_TWIDDLES \
    constexpr float COS14[14] = { \
         1.0f,                 0.9009688679024191f,  0.6234898018587336f, \
         0.22252093395631445f,-0.22252093395631445f,-0.6234898018587336f, \
        -0.9009688679024191f, -1.0f,                -0.9009688679024191f, \
        -0.6234898018587336f, -0.22252093395631445f, 0.22252093395631445f, \
         0.6234898018587336f,  0.9009688679024191f }; \
    constexpr float SIN14[14] = { \
         0.0f,                 0.43388373911755823f, 0.7818314824680298f, \
         0.9749279121818236f,  0.9749279121818236f,  0.7818314824680298f, \
         0.43388373911755823f, 0.0f,                -0.43388373911755823f, \
        -0.7818314824680298f, -0.9749279121818236f, -0.9749279121818236f, \
        -0.7818314824680298f, -0.43388373911755823f }

__global__ __launch_bounds__(NTH, 4)
void gfilter_kernel(const float* __restrict__ x,
                    const float* __restrict__ wt,
                    float* __restrict__ y)
{
    DEF_TWIDDLES;
    constexpr float INV98  = 1.0f / 98.0f;
    constexpr float INV196 = 1.0f / 196.0f;
    extern __shared__ ull sbuf[];   // 112 slots x 32 channels, 8B each

    const int tid  = threadIdx.x;
    const int cl   = tid & 31;
    const int role = tid >> 5;      // 0..7, one warp per role
    const int b    = blockIdx.y;
    const int c    = blockIdx.x * CB + cl;

    ull* bufc = sbuf + cl;          // index: slot*32; slot = h*8 + kw
    const int base = (b * 196) * CC + c;
    const float* xb = x + base;

    // ---- Pass A: rfft over W, double-folded --------------------------------
    #pragma unroll
    for (int i = 0; i < 2; ++i) {
        const int h = role + 8 * i;
        if (i == 0 || role < 6) {
            float xv[14];
            #pragma unroll
            for (int w = 0; w < 14; ++w)
                xv[w] = __ldg(&xb[(h * 14 + w) * CC]);
            ull eo[7];
            #pragma unroll
            for (int j = 1; j <= 6; ++j)
                eo[j] = pk(xv[j] + xv[14 - j], xv[j] - xv[14 - j]);
            const float be = xv[0] + xv[7], bo = xv[0] - xv[7];
            // second fold over j ~ 7-j (packed: +e/-o for even kw, -e/+o for odd)
            ull eoP[4], eoM[4];
            #pragma unroll
            for (int j = 1; j <= 3; ++j) {
                eoP[j] = f2fma(eo[7 - j], pkc( 1.f, -1.f), eo[j]);
                eoM[j] = f2fma(eo[7 - j], pkc(-1.f,  1.f), eo[j]);
            }
            #pragma unroll
            for (int kw = 0; kw < 8; ++kw) {
                ull acc = pk((kw & 1) ? bo : be, 0.f);   // (re, im)
                #pragma unroll
                for (int j = 1; j <= 3; ++j) {
                    const int m = (kw * j) % 14;
                    acc = f2fma((kw & 1) ? eoM[j] : eoP[j],
                                pkc(COS14[m], -SIN14[m]), acc);
                }
                bufc[(h * 8 + kw) * 32] = acc;
            }
        }
    }
    __syncthreads();

    // ---- Pass B: fwd H-DFT + weight + inv H-DFT, double-folded -------------
    {
        const int kw = role;
        ull F[14];
        #pragma unroll
        for (int h = 0; h < 14; ++h)
            F[h] = bufc[(h * 8 + kw) * 32];

        // fold1: E (even), OS = swapped odd
        ull E[7], OS[7];
        #pragma unroll
        for (int j = 1; j <= 6; ++j) {
            E[j]  = f2add(F[j], F[14 - j]);
            OS[j] = swp(f2sub(F[j], F[14 - j]));
        }
        const ull fbp = f2add(F[0], F[7]);
        const ull fbm = f2sub(F[0], F[7]);
        // fold2: cos-rule (+ for even kh), sin-rule (- for even kh)
        ull EP[4], EM[4], OSM[4], OSP[4];
        #pragma unroll
        for (int j = 1; j <= 3; ++j) {
            EP[j]  = f2add(E[j],  E[7 - j]);
            EM[j]  = f2sub(E[j],  E[7 - j]);
            OSM[j] = f2sub(OS[j], OS[7 - j]);
            OSP[j] = f2add(OS[j], OS[7 - j]);
        }

        const float2* wt2c = reinterpret_cast<const float2*>(wt) + c;

        // forward per kh-pair: T = (Si,-Sr); X[kh]=C+T, X[14-kh]=C-T
        ull X0, X7, EZ[7], OZS[7];
        #pragma unroll
        for (int kh = 0; kh < 8; ++kh) {
            ull Cacc = (kh & 1) ? fbm : fbp;
            ull Tacc = 0ull;
            #pragma unroll
            for (int j = 1; j <= 3; ++j) {
                const int m = (kh * j) % 14;
                Cacc = f2fma((kh & 1) ? EM[j] : EP[j], CP(COS14[m]), Cacc);
                if ((kh % 7) != 0)   // sins vanish only at kh = 0, 7
                    Tacc = f2fma((kh & 1) ? OSP[j] : OSM[j],
                                 pkc(SIN14[m], -SIN14[m]), Tacc);
            }
            ull Xa = cmulw(f2add(Cacc, Tacc),
                           pk(wt2c[(kh * 8 + kw) * CC].x,
                              wt2c[(kh * 8 + kw) * CC].y));
            if (kh == 0)      X0 = Xa;
            else if (kh == 7) X7 = Xa;
            else {
                ull Xb = cmulw(f2sub(Cacc, Tacc),
                               pk(wt2c[((14 - kh) * 8 + kw) * CC].x,
                                  wt2c[((14 - kh) * 8 + kw) * CC].y));
                EZ[kh]  = f2add(Xa, Xb);
                OZS[kh] = swp(f2sub(Xa, Xb));
            }
        }
        // inverse: fold2 on EZ/OZS, then 3-term sums per h
        const ull ibp = f2add(X0, X7);
        const ull ibm = f2sub(X0, X7);
        ull EZP[4], EZM[4], OZM[4], OZP[4];
        #pragma unroll
        for (int j = 1; j <= 3; ++j) {
            EZP[j] = f2add(EZ[j],  EZ[7 - j]);
            EZM[j] = f2sub(EZ[j],  EZ[7 - j]);
            OZM[j] = f2sub(OZS[j], OZS[7 - j]);
            OZP[j] = f2add(OZS[j], OZS[7 - j]);
        }
        #pragma unroll
        for (int h = 0; h < 8; ++h) {
            ull Cacc = (h & 1) ? ibm : ibp;
            ull Tacc = 0ull;
            #pragma unroll
            for (int j = 1; j <= 3; ++j) {
                const int m = (j * h) % 14;
                Cacc = f2fma((h & 1) ? EZM[j] : EZP[j], CP(COS14[m]), Cacc);
                if ((h % 7) != 0)
                    Tacc = f2fma((h & 1) ? OZP[j] : OZM[j],
                                 pkc(SIN14[m], -SIN14[m]), Tacc);
            }
            bufc[(h * 8 + kw) * 32] = f2sub(Cacc, Tacc);
            if (h >= 1 && h <= 6)
                bufc[((14 - h) * 8 + kw) * 32] = f2add(Cacc, Tacc);
        }
    }
    __syncthreads();

    // ---- Pass C: c2r over W, double-folded, scale in constants -------------
    float* yb = y + base;
    #pragma unroll
    for (int i = 0; i < 2; ++i) {
        const int h = role + 8 * i;
        if (i == 0 || role < 6) {
            ull yv[8];
            #pragma unroll
            for (int kw = 0; kw < 8; ++kw)
                yv[kw] = bufc[(h * 8 + kw) * 32];
            float yr0, yi0, yr7, yi7;
            upk(yv[0], yr0, yi0); upk(yv[7], yr7, yi7);
            const float b0 = yr0 * INV196, b7 = yr7 * INV196;
            const float bse_e = b0 + b7, bse_o = b0 - b7;
            // fold2 over kw ~ 7-kw (C-lane +, S-lane - for even w)
            ull yP[4], yM[4];
            #pragma unroll
            for (int kw = 1; kw <= 3; ++kw) {
                yP[kw] = f2fma(yv[7 - kw], pkc( 1.f, -1.f), yv[kw]);
                yM[kw] = f2fma(yv[7 - kw], pkc(-1.f,  1.f), yv[kw]);
            }
            #pragma unroll
            for (int w = 0; w < 8; ++w) {
                ull acc = pk((w & 1) ? bse_o : bse_e, 0.f);  // (C, S)
                #pragma unroll
                for (int kw = 1; kw <= 3; ++kw) {
                    const int m = (kw * w) % 14;
                    acc = f2fma((w & 1) ? yM[kw] : yP[kw],
                                pkc(COS14[m] * INV98, SIN14[m] * INV98), acc);
                }
                float Cv, Sv; upk(acc, Cv, Sv);
                stcs(&yb[(h * 14 + w) * CC], Cv - Sv);
                if (w >= 1 && w <= 6)
                    stcs(&yb[(h * 14 + 14 - w) * CC], Cv + Sv);
            }
        }
    }
}

extern "C" void kernel_launch(void* const* d_in, const int* in_sizes, int n_in,
                              void* d_out, int out_size)
{
    (void)in_sizes; (void)n_in; (void)out_size;
    const float* x  = (const float*)d_in[0];
    const float* wt = (const float*)d_in[1];
    float* y        = (float*)d_out;

    const int smem_bytes = 112 * CB * (int)sizeof(ull); // 28672
    dim3 grid(CC / CB, 128); // (24, 128)
    gfilter_kernel<<<grid, NTH, smem_bytes>>>(x, wt, y);
}